// round 16
// baseline (speedup 1.0000x reference)
#include <cuda_runtime.h>
#include <cuda_fp16.h>
#include <cstdint>

#define NB   4
#define SEQ  2048
#define NH   16
#define DEP  64
#define DM   1024
#define MROWS (NB*SEQ)

typedef unsigned short u16;
typedef unsigned int   u32;

// ---------------- scratch ----------------
__device__ u16 g_w16[4][(size_t)DM*DM];          // weights fp16 (single plane)
__device__ u16 g_q16[(size_t)MROWS*DM];          // fp16 head planes [B,H,S,64]
__device__ u16 g_k16[(size_t)MROWS*DM];
__device__ u16 g_v16[(size_t)MROWS*DM];
__device__ u16 g_c16[(size_t)MROWS*DM];          // ctx fp16 [B,S,DM]

// ---------------- helpers ----------------
__device__ __forceinline__ unsigned smem_u32(const void* p) {
    unsigned r;
    asm("{ .reg .u64 t; cvta.to.shared.u64 t, %1; cvt.u32.u64 %0, t; }"
        : "=r"(r) : "l"(p));
    return r;
}

__device__ __forceinline__ void ldsm4(u32& r0, u32& r1, u32& r2, u32& r3,
                                      unsigned addr) {
    asm volatile("ldmatrix.sync.aligned.m8n8.x4.shared.b16 {%0,%1,%2,%3}, [%4];"
                 : "=r"(r0), "=r"(r1), "=r"(r2), "=r"(r3) : "r"(addr));
}
__device__ __forceinline__ void ldsm4t(u32& r0, u32& r1, u32& r2, u32& r3,
                                       unsigned addr) {
    asm volatile("ldmatrix.sync.aligned.m8n8.x4.trans.shared.b16 {%0,%1,%2,%3}, [%4];"
                 : "=r"(r0), "=r"(r1), "=r"(r2), "=r"(r3) : "r"(addr));
}
// fp16 mma
__device__ __forceinline__ void mma16816h(float* d, const u32* a, const u32* b) {
    asm volatile("mma.sync.aligned.m16n8k16.row.col.f32.f16.f16.f32 "
                 "{%0,%1,%2,%3}, {%4,%5,%6,%7}, {%8,%9}, {%0,%1,%2,%3};"
                 : "+f"(d[0]), "+f"(d[1]), "+f"(d[2]), "+f"(d[3])
                 : "r"(a[0]), "r"(a[1]), "r"(a[2]), "r"(a[3]),
                   "r"(b[0]), "r"(b[1]));
}

#define CP_ASYNC16(dst, src) \
    asm volatile("cp.async.cg.shared.global [%0], [%1], 16;" :: "r"(dst), "l"(src))
#define CP_COMMIT() asm volatile("cp.async.commit_group;" ::: "memory")
#define CP_WAIT0()  asm volatile("cp.async.wait_group 0;" ::: "memory")
#define CP_WAIT1()  asm volatile("cp.async.wait_group 1;" ::: "memory")

// 2^x via MUFU (exp folded: q pre-scaled by 0.125*log2e)
__device__ __forceinline__ float fex2(float x) {
    float r; asm("ex2.approx.f32 %0, %1;" : "=f"(r) : "f"(x)); return r;
}

// pack two fp32 -> fp16x2 (RN): lo = a, hi = b
__device__ __forceinline__ u32 packh2(float a, float b) {
    u32 d; asm("cvt.rn.f16x2.f32 %0, %1, %2;" : "=r"(d) : "f"(b), "f"(a));
    return d;
}

// ---------------- weight conversion (all 4 weights, single fp16 plane) ----
__global__ void conv_w16(const float4* __restrict__ w0,
                         const float4* __restrict__ w1,
                         const float4* __restrict__ w2,
                         const float4* __restrict__ w3,
                         uint2* __restrict__ out, int n4)
{
    int i = blockIdx.x * blockDim.x + threadIdx.x;
    if (i >= n4) return;
    int z = blockIdx.y;
    const float4* src = (z == 0) ? w0 : (z == 1) ? w1 : (z == 2) ? w2 : w3;
    float4 v = src[i];
    out[(size_t)z * (DM*DM/4) + i] =
        make_uint2(packh2(v.x, v.y), packh2(v.z, v.w));
}

// ---------------- GEMM common geometry ----------------
// 128x128 tile, BK=32, 8 warps (2x4). Stage: A fp16 [128][40] + W fp16 [128][40].
// 3-stage cp.async ring, wait_group 1, ONE barrier per chunk.
#define GP 40
#define STAGE_B 20480
#define GSMEM_BYTES (3*STAGE_B)

// ---------------- fused QKV projection: fp32 A in, fp16 head planes out ---
__global__ void __launch_bounds__(256, 2) gemm_qkv(
    const float* __restrict__ Aq, const float* __restrict__ Ak,
    const float* __restrict__ Av,
    const u16* __restrict__ WA,
    const float* __restrict__ bq, const float* __restrict__ bk,
    const float* __restrict__ bv,
    u16* __restrict__ Oq, u16* __restrict__ Ok, u16* __restrict__ Ov,
    float qscale)
{
    extern __shared__ char gsm[];
    const unsigned sbase = smem_u32(gsm);
    const int tid  = threadIdx.x;
    const int lane = tid & 31;
    const int warp = tid >> 5;
    const int warp_m = warp & 1, warp_n = warp >> 1;
    const int bn = blockIdx.x, bm = blockIdx.y, z = blockIdx.z;

    const float* A32 = ((z == 0) ? Aq : (z == 1) ? Ak : Av)
                     + (size_t)(bm * 128) * DM;
    const u16* W = WA + (size_t)z * DM * DM + (size_t)(bn * 128) * DM;
    const float* bias = (z == 0) ? bq : (z == 1) ? bk : bv;
    u16* C16 = (z == 0) ? Oq : (z == 1) ? Ok : Ov;
    const float scale = (z == 0) ? qscale : 1.0f;

    const int trow = tid >> 2;          // 0..63 (W loader)
    const int tc16 = tid & 3;
    const int arow = tid >> 3;          // 0..31 (A loader)
    const int af4  = tid & 7;

    float acc[4][4][4];
#pragma unroll
    for (int i = 0; i < 4; i++)
#pragma unroll
        for (int j = 0; j < 4; j++)
#pragma unroll
            for (int t = 0; t < 4; t++) acc[i][j][t] = 0.f;

    const unsigned OFF_A = 0, OFF_W = 10240;
    const unsigned a_row = warp_m*64 + (lane & 15);
    const unsigned a_kof = (lane >> 4) * 8;
    const unsigned b_row = warp_n*32 + (lane & 7) + ((lane & 16) >> 1);
    const unsigned b_kof = (lane & 8);

#define QKV_WISSUE(chunk, stage) do { \
    unsigned _db = sbase + (stage)*STAGE_B; \
    int _ck = (chunk) * 32; \
    _Pragma("unroll") \
    for (int _i = 0; _i < 2; _i++) { \
        int _row = (_i << 6) + trow; \
        const u16* _s = W + (size_t)_row * DM + _ck + tc16 * 8; \
        unsigned _d = _db + OFF_W + _row * 80 + tc16 * 16; \
        CP_ASYNC16(_d, _s); \
    } \
    CP_COMMIT(); \
} while (0)

    float4 pa[4];
#define QKV_ALDG(chunk) do { \
    int _ck = (chunk) * 32; \
    _Pragma("unroll") \
    for (int _p = 0; _p < 4; _p++) { \
        int _row = _p*32 + arow; \
        pa[_p] = *(const float4*)(A32 + (size_t)_row * DM + _ck + af4*4); \
    } \
} while (0)

#define QKV_ASTS(stage) do { \
    char* _sp = gsm + (stage)*STAGE_B + OFF_A; \
    _Pragma("unroll") \
    for (int _p = 0; _p < 4; _p++) { \
        int _row = _p*32 + arow; \
        *(uint2*)(_sp + _row*80 + af4*8) = \
            make_uint2(packh2(pa[_p].x, pa[_p].y), packh2(pa[_p].z, pa[_p].w)); \
    } \
} while (0)

    QKV_WISSUE(0, 0);
    QKV_WISSUE(1, 1);
    QKV_ALDG(0);

    const int NCHUNK = DM / 32;   // 32
    for (int c = 0; c < NCHUNK; c++) {
        const int st = c % 3;
        QKV_ASTS(st);                      // stage st: no live readers (see proof)
        if (c < NCHUNK - 1) CP_WAIT1(); else CP_WAIT0();
        __syncthreads();                   // W chunk c + all ASTS visible
        if (c + 2 < NCHUNK) QKV_WISSUE(c + 2, (c + 2) % 3);
        if (c + 1 < NCHUNK) QKV_ALDG(c + 1);

        const unsigned sb = sbase + (unsigned)st * STAGE_B;
#pragma unroll
        for (int ks = 0; ks < 2; ks++) {
            const unsigned kbyte = (unsigned)(ks * 16) * 2;
            u32 bh[8];
#pragma unroll
            for (int jp = 0; jp < 2; jp++) {
                unsigned roff = (b_row + jp*16) * (GP*2) + kbyte + b_kof*2;
                ldsm4(bh[jp*4+0], bh[jp*4+1], bh[jp*4+2], bh[jp*4+3],
                      sb + OFF_W + roff);
            }
#pragma unroll
            for (int i = 0; i < 4; i++) {
                unsigned roff = (a_row + i*16) * (GP*2) + kbyte + a_kof*2;
                u32 ah[4];
                ldsm4(ah[0], ah[1], ah[2], ah[3], sb + OFF_A + roff);
#pragma unroll
                for (int j = 0; j < 4; j++)
                    mma16816h(acc[i][j], ah, &bh[j*2]);
            }
        }
        // no bottom barrier: next iter's writes touch different stages
    }

    // epilogue: fp16 head plane [B,H,S,64]
    const int gid = lane >> 2, tig = lane & 3;
#pragma unroll
    for (int i = 0; i < 4; i++) {
#pragma unroll
        for (int j = 0; j < 4; j++) {
            int gnc = bn*128 + warp_n*32 + j*8 + tig*2;
            float2 bv = *(const float2*)(bias + gnc);
#pragma unroll
            for (int half = 0; half < 2; half++) {
                int m = bm*128 + warp_m*64 + i*16 + gid + half*8;
                float o0 = (acc[i][j][half*2+0] + bv.x) * scale;
                float o1 = (acc[i][j][half*2+1] + bv.y) * scale;
                int bi = m >> 11, s = m & (SEQ - 1);
                int hh = gnc >> 6, d = gnc & 63;
                size_t idx = (((size_t)(bi*NH + hh) * SEQ + s) << 6) + d;
                *(u32*)(C16 + idx) = packh2(o0, o1);
            }
        }
    }
}

// ---------------- output GEMM: fp16 A via cp.async, fp32 out -------------
#define GEMM_ISSUE(chunk, stage) do { \
    unsigned _db = sbase + (stage)*STAGE_B; \
    int _ck = (chunk) * 32; \
    _Pragma("unroll") \
    for (int _i = 0; _i < 4; _i++) { \
        int _pl = _i >> 1; \
        int _row = ((_i & 1) << 6) + trow; \
        const u16* _s = srcs[_pl] + (size_t)_row * DM + _ck + tc16 * 8; \
        unsigned _d = _db + _pl * 10240 + _row * 80 + tc16 * 16; \
        CP_ASYNC16(_d, _s); \
    } \
    CP_COMMIT(); \
} while (0)

__global__ void __launch_bounds__(256, 2) gemm_out(
    const u16* __restrict__ A16, const u16* __restrict__ W,
    const float* __restrict__ bias, float* __restrict__ Cf)
{
    extern __shared__ char gsm[];
    const unsigned sbase = smem_u32(gsm);
    const int tid  = threadIdx.x;
    const int lane = tid & 31;
    const int warp = tid >> 5;
    const int warp_m = warp & 1, warp_n = warp >> 1;
    const int bn = blockIdx.x, bm = blockIdx.y;

    const u16* srcs[2];
    srcs[0] = A16 + (size_t)(bm * 128) * DM;
    srcs[1] = W   + (size_t)(bn * 128) * DM;

    const int trow = tid >> 2;
    const int tc16 = tid & 3;

    float acc[4][4][4];
#pragma unroll
    for (int i = 0; i < 4; i++)
#pragma unroll
        for (int j = 0; j < 4; j++)
#pragma unroll
            for (int t = 0; t < 4; t++) acc[i][j][t] = 0.f;

    const unsigned OFF_A = 0, OFF_W = 10240;
    const unsigned a_row = warp_m*64 + (lane & 15);
    const unsigned a_kof = (lane >> 4) * 8;
    const unsigned b_row = warp_n*32 + (lane & 7) + ((lane & 16) >> 1);
    const unsigned b_kof = (lane & 8);

    GEMM_ISSUE(0, 0);
    GEMM_ISSUE(1, 1);

    const int NCHUNK = DM / 32;
    for (int c = 0; c < NCHUNK; c++) {
        if (c < NCHUNK - 1) CP_WAIT1(); else CP_WAIT0();
        __syncthreads();
        if (c + 2 < NCHUNK) GEMM_ISSUE(c + 2, (c + 2) % 3);

        const unsigned st = sbase + (unsigned)(c % 3) * STAGE_B;
#pragma unroll
        for (int ks = 0; ks < 2; ks++) {
            const unsigned kbyte = (unsigned)(ks * 16) * 2;
            u32 bh[8];
#pragma unroll
            for (int jp = 0; jp < 2; jp++) {
                unsigned roff = (b_row + jp*16) * (GP*2) + kbyte + b_kof*2;
                ldsm4(bh[jp*4+0], bh[jp*4+1], bh[jp*4+2], bh[jp*4+3],
                      st + OFF_W + roff);
            }
#pragma unroll
            for (int i = 0; i < 4; i++) {
                unsigned roff = (a_row + i*16) * (GP*2) + kbyte + a_kof*2;
                u32 ah[4];
                ldsm4(ah[0], ah[1], ah[2], ah[3], st + OFF_A + roff);
#pragma unroll
                for (int j = 0; j < 4; j++)
                    mma16816h(acc[i][j], ah, &bh[j*2]);
            }
        }
    }

    const int gid = lane >> 2, tig = lane & 3;
#pragma unroll
    for (int i = 0; i < 4; i++) {
#pragma unroll
        for (int j = 0; j < 4; j++) {
            int gnc = bn*128 + warp_n*32 + j*8 + tig*2;
            float2 bv = *(const float2*)(bias + gnc);
#pragma unroll
            for (int half = 0; half < 2; half++) {
                int m = bm*128 + warp_m*64 + i*16 + gid + half*8;
                float o0 = acc[i][j][half*2+0] + bv.x;
                float o1 = acc[i][j][half*2+1] + bv.y;
                *(float2*)(Cf + (size_t)m * DM + gnc) = make_float2(o0, o1);
            }
        }
    }
}

// ---------------- attention: fused per-group QK->exp->PV ----------------
#define AQ 0
#define ABUF0 18432
#define ABUF1 36864
#define ASMEM_BYTES 55296

__global__ void __launch_bounds__(256, 2) attn_mma_kernel(
    const u16* __restrict__ Qh, const u16* __restrict__ Kh,
    const u16* __restrict__ Vh, u16* __restrict__ C16)
{
    extern __shared__ char asm_[];
    const unsigned sbase = smem_u32(asm_);
    const int tid  = threadIdx.x;
    const int lane = tid & 31;
    const int w    = tid >> 5;
    const int gid  = lane >> 2, tig = lane & 3;
    const int qt = blockIdx.x, h = blockIdx.y, b = blockIdx.z;
    const size_t bh = (size_t)(b*NH + h) * SEQ;

    const int unit = tid >> 1;
    const int uhalf = tid & 1;

    // KV tile 0
    {
        const u16* pl = (unit < 64) ? Kh : Vh;
        int row = unit & 63;
        const u16* src = pl + ((bh + row) << 6) + uhalf*32;
        unsigned dst = sbase + ABUF0 + ((unit < 64) ? 0u : 9216u)
                     + row*144 + uhalf*64;
#pragma unroll
        for (int i = 0; i < 4; i++) CP_ASYNC16(dst + i*16, src + i*8);
    }
    // Q tile
    {
        const u16* src = Qh + ((bh + qt*128 + unit) << 6) + uhalf*32;
        unsigned dst = sbase + AQ + unit*144 + uhalf*64;
#pragma unroll
        for (int i = 0; i < 4; i++) CP_ASYNC16(dst + i*16, src + i*8);
    }
    CP_COMMIT();
    CP_WAIT0();
    __syncthreads();

    u32 qf[4][4];
    {
        unsigned rbase = (unsigned)(w*16 + (lane & 15)) * 144 + (lane >> 4) * 16;
#pragma unroll
        for (int ks = 0; ks < 4; ks++)
            ldsm4(qf[ks][0], qf[ks][1], qf[ks][2], qf[ks][3],
                  sbase + AQ + rbase + ks*32);
    }

    float o_[8][4];
#pragma unroll
    for (int j = 0; j < 8; j++)
#pragma unroll
        for (int t = 0; t < 4; t++) o_[j][t] = 0.f;
    float l0 = 0.f, l1 = 0.f;

    const unsigned b_rowoff = ((lane & 7) + ((lane & 16) >> 1)) * 144 + (lane & 8) * 2;
    const unsigned v_rowoff = (lane & 15) * 144 + (lane >> 4) * 16;

    for (int kt = 0; kt < SEQ/64; kt++) {
        const unsigned cbuf = (kt & 1) ? ABUF1 : ABUF0;

        if (kt + 1 < SEQ/64) {
            const u16* pl = (unit < 64) ? Kh : Vh;
            int row = unit & 63;
            const u16* src = pl + ((bh + (kt+1)*64 + row) << 6) + uhalf*32;
            unsigned dst = sbase + ((kt & 1) ? ABUF0 : ABUF1)
                         + ((unit < 64) ? 0u : 9216u) + row*144 + uhalf*64;
#pragma unroll
            for (int i = 0; i < 4; i++) CP_ASYNC16(dst + i*16, src + i*8);
            CP_COMMIT();
        }

        u32 kf[4][4];
#pragma unroll
        for (int ks = 0; ks < 4; ks++)
            ldsm4(kf[ks][0], kf[ks][1], kf[ks][2], kf[ks][3],
                  sbase + cbuf + b_rowoff + ks*32);

#pragma unroll
        for (int g = 0; g < 4; g++) {
            u32 vf[4][4];
            unsigned vbase = (unsigned)(g*16)*144 + v_rowoff;
#pragma unroll
            for (int ngv = 0; ngv < 4; ngv++)
                ldsm4t(vf[ngv][0], vf[ngv][1], vf[ngv][2], vf[ngv][3],
                       sbase + cbuf + 9216u + vbase + ngv*32);

            float s0[4] = {0.f, 0.f, 0.f, 0.f};
            float s1[4] = {0.f, 0.f, 0.f, 0.f};
#pragma unroll
            for (int ks = 0; ks < 4; ks++) {
                mma16816h(s0, qf[ks], &kf[ks][0]);
                mma16816h(s1, qf[ks], &kf[ks][2]);
            }

            if (g < 3) {
                unsigned roff = (unsigned)((g+1)*16)*144 + b_rowoff;
#pragma unroll
                for (int ks = 0; ks < 4; ks++)
                    ldsm4(kf[ks][0], kf[ks][1], kf[ks][2], kf[ks][3],
                          sbase + cbuf + roff + ks*32);
            }

            float p0 = fex2(s0[0]), p1 = fex2(s0[1]);
            float p2 = fex2(s0[2]), p3 = fex2(s0[3]);
            float q0 = fex2(s1[0]), q1 = fex2(s1[1]);
            float q2 = fex2(s1[2]), q3 = fex2(s1[3]);
            l0 += (p0 + p1) + (q0 + q1);
            l1 += (p2 + p3) + (q2 + q3);
            u32 pa[4];
            pa[0] = packh2(p0, p1);
            pa[1] = packh2(p2, p3);
            pa[2] = packh2(q0, q1);
            pa[3] = packh2(q2, q3);

#pragma unroll
            for (int ngv = 0; ngv < 4; ngv++) {
                mma16816h(o_[2*ngv+0], pa, &vf[ngv][0]);
                mma16816h(o_[2*ngv+1], pa, &vf[ngv][2]);
            }
        }

        CP_WAIT0();
        __syncthreads();
    }

    l0 += __shfl_xor_sync(0xffffffffu, l0, 1);
    l0 += __shfl_xor_sync(0xffffffffu, l0, 2);
    l1 += __shfl_xor_sync(0xffffffffu, l1, 1);
    l1 += __shfl_xor_sync(0xffffffffu, l1, 2);

    float inv0 = 1.f / l0, inv1 = 1.f / l1;
    int r0 = qt*128 + w*16 + gid;
    size_t base0 = ((size_t)(b*SEQ) + r0) * DM + h*64;
    size_t base1 = base0 + (size_t)8 * DM;
#pragma unroll
    for (int j = 0; j < 8; j++) {
        int d = j*8 + tig*2;
        *(u32*)(C16 + base0 + d) = packh2(o_[j][0]*inv0, o_[j][1]*inv0);
        *(u32*)(C16 + base1 + d) = packh2(o_[j][2]*inv1, o_[j][3]*inv1);
    }
}

// ---------------- launch ----------------
extern "C" void kernel_launch(void* const* d_in, const int* in_sizes, int n_in,
                              void* d_out, int out_size)
{
    const float* q    = (const float*)d_in[0];
    const float* k    = (const float*)d_in[1];
    const float* v    = (const float*)d_in[2];
    const float* wq_w = (const float*)d_in[3];
    const float* wq_b = (const float*)d_in[4];
    const float* wk_w = (const float*)d_in[5];
    const float* wk_b = (const float*)d_in[6];
    const float* wv_w = (const float*)d_in[7];
    const float* wv_b = (const float*)d_in[8];
    const float* wo_w = (const float*)d_in[9];
    const float* wo_b = (const float*)d_in[10];
    float* out = (float*)d_out;

    u16 *w16, *q16, *k16, *v16, *c16;
    cudaGetSymbolAddress((void**)&w16, g_w16);
    cudaGetSymbolAddress((void**)&q16, g_q16);
    cudaGetSymbolAddress((void**)&k16, g_k16);
    cudaGetSymbolAddress((void**)&v16, g_v16);
    cudaGetSymbolAddress((void**)&c16, g_c16);
    const size_t WSZ = (size_t)DM * DM;

    cudaFuncSetAttribute(gemm_qkv,
                         cudaFuncAttributeMaxDynamicSharedMemorySize, GSMEM_BYTES);
    cudaFuncSetAttribute(gemm_out,
                         cudaFuncAttributeMaxDynamicSharedMemorySize, GSMEM_BYTES);
    cudaFuncSetAttribute(attn_mma_kernel,
                         cudaFuncAttributeMaxDynamicSharedMemorySize, ASMEM_BYTES);

    const int nW4 = DM*DM/4;
    const int cblk = 256;
    const int cgW = (nW4 + cblk - 1) / cblk;

    dim3 wgrid(cgW, 4);
    conv_w16<<<wgrid, cblk>>>((const float4*)wq_w, (const float4*)wk_w,
                              (const float4*)wv_w, (const float4*)wo_w,
                              (uint2*)w16, nW4);

    const float QSCALE = 0.125f * 1.4426950408889634f;
    dim3 gblk(256), qgrid(DM/128, MROWS/128, 3);
    gemm_qkv<<<qgrid, gblk, GSMEM_BYTES>>>(q, k, v, w16,
                                           wq_b, wk_b, wv_b,
                                           q16, k16, v16, QSCALE);

    dim3 ablk(256), agrid(SEQ/128, NH, NB);
    attn_mma_kernel<<<agrid, ablk, ASMEM_BYTES>>>(q16, k16, v16, c16);

    dim3 ogrid(DM/128, MROWS/128);
    gemm_out<<<ogrid, gblk, GSMEM_BYTES>>>(c16, w16 + 3*WSZ, wo_b, out);
}